// round 2
// baseline (speedup 1.0000x reference)
#include <cuda_runtime.h>
#include <cstdint>
#include <cstddef>

// VectorQuantizer: z[B,512] fp32, emb[K,512] fp32
//   d2[b,k] = ||z_b||^2 - 2 z_b.e_k + ||e_k||^2 ; idx = argmin_k (first-index ties)
//   z_q_st = z + (emb[idx] - z)  (literal fp32 op order, matches straight-through)
//   vq_loss = 1.25 * mean((emb[idx]-z)^2)
// Output layout (float32): [ z_q_st (B*512) | indices (B) | vq_loss (1) ], guarded by out_size.

#define DDIM 512
#define BM 64
#define BN 128
#define BD 16

__device__ float  g_ee[8192];
__device__ float  g_zz[16384];
__device__ int    g_best[16384];
__device__ double g_part[512];

// -------------------------------------------------------------------------
// Row squared norms: one warp per row, covers emb rows then z rows.
// -------------------------------------------------------------------------
__global__ void rowsq_kernel(const float* __restrict__ emb,
                             const float* __restrict__ z,
                             int K, int B)
{
    int w    = (blockIdx.x * blockDim.x + threadIdx.x) >> 5;
    int lane = threadIdx.x & 31;
    if (w >= K + B) return;
    const float* src = (w < K) ? (emb + (size_t)w * DDIM)
                               : (z   + (size_t)(w - K) * DDIM);
    float s = 0.f;
#pragma unroll
    for (int t = 0; t < DDIM / 32; t++) {
        float x = src[lane + 32 * t];
        s = fmaf(x, x, s);
    }
#pragma unroll
    for (int off = 16; off > 0; off >>= 1)
        s += __shfl_xor_sync(0xFFFFFFFFu, s, off);
    if (lane == 0) {
        if (w < K) g_ee[w] = s;
        else       g_zz[w - K] = s;
    }
}

// -------------------------------------------------------------------------
// Main fused GEMM + argmin.
//   Each block owns BM=64 z-rows, loops over all K in BN=128 tiles,
//   accumulating the full D=512 dot product per tile (BD=16 double-buffered),
//   then folds d2 into a running per-row (min, argmin).
// Thread layout: 256 threads = 16(tx) x 16(ty); micro-tile 4 rows x 8 cols,
//   cols split as {tx*4..tx*4+3} and {64+tx*4..64+tx*4+3} for conflict-free LDS.128.
// -------------------------------------------------------------------------
__global__ __launch_bounds__(256, 2)
void vq_argmin_kernel(const float* __restrict__ z,
                      const float* __restrict__ emb,
                      int K)
{
    __shared__ float sA[2][BD][BM + 4];
    __shared__ float sB[2][BD][BN + 4];
    __shared__ float sEE[BN];

    const int tid  = threadIdx.x;
    const int tx   = tid & 15;
    const int ty   = tid >> 4;
    const int brow = blockIdx.x * BM;

    float zz_r[4];
#pragma unroll
    for (int i = 0; i < 4; i++) zz_r[i] = g_zz[brow + ty * 4 + i];

    float bestv[4];
    int   besti[4];
#pragma unroll
    for (int i = 0; i < 4; i++) { bestv[i] = 3.4e38f; besti[i] = 0; }

    // global->smem load mapping (float4 granularity)
    const int arow = tid >> 2;   // 0..63
    const int aseg = tid & 3;    // 0..3  (4 floats each)
    const float* zbase = z + (size_t)(brow + arow) * DDIM + aseg * 4;
    const int erow = tid >> 2;   // 0..63 (and erow+64 for second half)
    const int eseg = tid & 3;

    for (int kt = 0; kt < K; kt += BN) {
        __syncthreads();                       // prev-iter smem reads done
        if (tid < BN) sEE[tid] = g_ee[kt + tid];

        const float* ebase = emb + (size_t)kt * DDIM;

        float acc[4][8];
#pragma unroll
        for (int i = 0; i < 4; i++)
#pragma unroll
            for (int j = 0; j < 8; j++) acc[i][j] = 0.f;

        // prologue: stage dt = 0 into buffer 0
        float4 na  = *(const float4*)(zbase);
        float4 nb0 = *(const float4*)(ebase + (size_t)erow * DDIM + eseg * 4);
        float4 nb1 = *(const float4*)(ebase + (size_t)(erow + 64) * DDIM + eseg * 4);
        {
            int d0 = aseg * 4;
            sA[0][d0 + 0][arow] = na.x; sA[0][d0 + 1][arow] = na.y;
            sA[0][d0 + 2][arow] = na.z; sA[0][d0 + 3][arow] = na.w;
            int d1 = eseg * 4;
            sB[0][d1 + 0][erow] = nb0.x; sB[0][d1 + 1][erow] = nb0.y;
            sB[0][d1 + 2][erow] = nb0.z; sB[0][d1 + 3][erow] = nb0.w;
            sB[0][d1 + 0][erow + 64] = nb1.x; sB[0][d1 + 1][erow + 64] = nb1.y;
            sB[0][d1 + 2][erow + 64] = nb1.z; sB[0][d1 + 3][erow + 64] = nb1.w;
        }
        __syncthreads();

        const int NDT = DDIM / BD;  // 32
        for (int dt = 0; dt < NDT; dt++) {
            const int  cur  = dt & 1;
            const bool more = (dt + 1) < NDT;
            if (more) {   // prefetch next BD-slab into registers
                int dcol = (dt + 1) * BD;
                na  = *(const float4*)(zbase + dcol);
                nb0 = *(const float4*)(ebase + (size_t)erow * DDIM + dcol + eseg * 4);
                nb1 = *(const float4*)(ebase + (size_t)(erow + 64) * DDIM + dcol + eseg * 4);
            }
#pragma unroll
            for (int d = 0; d < BD; d++) {
                float4 a  = *(const float4*)&sA[cur][d][ty * 4];
                float4 b0 = *(const float4*)&sB[cur][d][tx * 4];
                float4 b1 = *(const float4*)&sB[cur][d][64 + tx * 4];
                float av[4] = {a.x, a.y, a.z, a.w};
                float bv[8] = {b0.x, b0.y, b0.z, b0.w, b1.x, b1.y, b1.z, b1.w};
#pragma unroll
                for (int i = 0; i < 4; i++)
#pragma unroll
                    for (int j = 0; j < 8; j++)
                        acc[i][j] = fmaf(av[i], bv[j], acc[i][j]);
            }
            if (more) {
                int nxt = cur ^ 1;
                int d0 = aseg * 4;
                sA[nxt][d0 + 0][arow] = na.x; sA[nxt][d0 + 1][arow] = na.y;
                sA[nxt][d0 + 2][arow] = na.z; sA[nxt][d0 + 3][arow] = na.w;
                int d1 = eseg * 4;
                sB[nxt][d1 + 0][erow] = nb0.x; sB[nxt][d1 + 1][erow] = nb0.y;
                sB[nxt][d1 + 2][erow] = nb0.z; sB[nxt][d1 + 3][erow] = nb0.w;
                sB[nxt][d1 + 0][erow + 64] = nb1.x; sB[nxt][d1 + 1][erow + 64] = nb1.y;
                sB[nxt][d1 + 2][erow + 64] = nb1.z; sB[nxt][d1 + 3][erow + 64] = nb1.w;
            }
            __syncthreads();
        }

        // epilogue: d2 = (zz - 2*G) + ee  (matches reference rounding), fold min
#pragma unroll
        for (int i = 0; i < 4; i++) {
            float v  = 3.4e38f;
            int   bi = 0;
#pragma unroll
            for (int j = 0; j < 8; j++) {
                int col = (j < 4) ? (tx * 4 + j) : (64 + tx * 4 + (j - 4));
                float vj = fmaf(-2.f, acc[i][j], zz_r[i]) + sEE[col];
                int   kj = kt + col;
                if (vj < v) { v = vj; bi = kj; }      // strict <: first index wins ties
            }
#pragma unroll
            for (int off = 1; off < 16; off <<= 1) {  // tx lanes share a warp
                float ov = __shfl_xor_sync(0xFFFFFFFFu, v, off);
                int   oi = __shfl_xor_sync(0xFFFFFFFFu, bi, off);
                if (ov < v || (ov == v && oi < bi)) { v = ov; bi = oi; }
            }
            if (v < bestv[i]) { bestv[i] = v; besti[i] = bi; }  // earlier kt wins ties
        }
    }

    if (tx == 0) {
#pragma unroll
        for (int i = 0; i < 4; i++)
            g_best[brow + ty * 4 + i] = besti[i];
    }
}

// -------------------------------------------------------------------------
// Gather z_q, emit z_q_st with the reference's exact fp32 op order, emit
// indices as float, and accumulate deterministic per-block loss partials.
// blockDim = 128 (one float4 per thread per row), 32 rows per block.
// -------------------------------------------------------------------------
__global__ void gather_loss_kernel(const float* __restrict__ z,
                                   const float* __restrict__ emb,
                                   float* __restrict__ out_zq,
                                   float* __restrict__ out_idx,
                                   int B)
{
    __shared__ double sred[128];
    const int tid = threadIdx.x;
    double lsum = 0.0;

    for (int r = 0; r < 32; r++) {
        int b   = blockIdx.x * 32 + r;
        int idx = g_best[b];
        if (tid == 0 && out_idx) out_idx[b] = (float)idx;

        float4 zv = ((const float4*)(z   + (size_t)b   * DDIM))[tid];
        float4 ev = ((const float4*)(emb + (size_t)idx * DDIM))[tid];
        float4 o;
        float dx;
        dx = ev.x - zv.x; o.x = zv.x + dx; lsum += (double)dx * (double)dx;
        dx = ev.y - zv.y; o.y = zv.y + dx; lsum += (double)dx * (double)dx;
        dx = ev.z - zv.z; o.z = zv.z + dx; lsum += (double)dx * (double)dx;
        dx = ev.w - zv.w; o.w = zv.w + dx; lsum += (double)dx * (double)dx;
        ((float4*)(out_zq + (size_t)b * DDIM))[tid] = o;
    }

    sred[tid] = lsum;
    __syncthreads();
#pragma unroll
    for (int s = 64; s > 0; s >>= 1) {
        if (tid < s) sred[tid] += sred[tid + s];
        __syncthreads();
    }
    if (tid == 0) g_part[blockIdx.x] = sred[0];
}

__global__ void finalize_kernel(float* __restrict__ out_loss, int nparts, double scale)
{
    double s = 0.0;
    for (int i = 0; i < nparts; i++) s += g_part[i];   // fixed order: deterministic
    *out_loss = (float)(s * scale);
}

// -------------------------------------------------------------------------
extern "C" void kernel_launch(void* const* d_in, const int* in_sizes, int n_in,
                              void* d_out, int out_size)
{
    const float* z   = (const float*)d_in[0];
    const float* emb = (const float*)d_in[1];
    int B = in_sizes[0] / DDIM;   // 16384
    int K = in_sizes[1] / DDIM;   // 8192

    float* out     = (float*)d_out;
    float* out_zq  = out;
    float* out_idx  = ((size_t)out_size >= (size_t)B * DDIM + (size_t)B)
                        ? out + (size_t)B * DDIM : nullptr;
    float* out_loss = ((size_t)out_size >= (size_t)B * DDIM + (size_t)B + 1)
                        ? out + (size_t)B * DDIM + B : nullptr;

    int totalw = K + B;
    rowsq_kernel<<<(totalw * 32 + 255) / 256, 256>>>(emb, z, K, B);
    vq_argmin_kernel<<<B / BM, 256>>>(z, emb, K);
    int gblocks = B / 32;
    gather_loss_kernel<<<gblocks, 128>>>(z, emb, out_zq, out_idx, B);
    if (out_loss)
        finalize_kernel<<<1, 1>>>(out_loss, gblocks, 1.25 / ((double)B * (double)DDIM));
}

// round 4
// speedup vs baseline: 1.7089x; 1.7089x over previous
#include <cuda_runtime.h>
#include <cstdint>
#include <cstddef>

// VectorQuantizer, two-phase:
//   Phase 1: tf32 tensor-core GEMM -> approx q[b,k] (stored) + per-row approx min.
//   Phase 2: exact fp32 rescue (bit-identical to the Round-2 passing chain) on all
//            candidates within MARGIN of the approx min -> exact argmin w/ ties.
// Output: [ z_q_st (B*512) | indices as float (B) | vq_loss (1) ]

#define DDIM 512
#define BM 128
#define BN 128
#define BD 32

#define NB 16384
#define NK 8192

#define ROWP 36
#define ABUF (128 * ROWP)        // 4608 floats (one operand tile)
#define BUFSZ (2 * ABUF)         // A+B per pipeline buffer
#define STAGE_OFF (2 * BUFSZ)    // staging region after the two buffers
#define STROW 132                // staging row stride (128 + 4 pad)

#define MARGIN 1.5e-3f

__device__ float  g_ee[NK];
__device__ float  g_zz[NB];
__device__ float  g_rmin[NB];
__device__ int    g_best[NB];
__device__ double g_part[512];

__device__ float  g_zt[NB * DDIM];   // tf32-rounded z
__device__ float  g_et[NK * DDIM];   // tf32-rounded emb
__device__ float  g_q[(size_t)NB * NK];   // approx q, 512 MB

// -------------------------------------------------------------------------
__global__ void split_tf32_kernel(const float* __restrict__ src,
                                  float* __restrict__ dst, int n4)
{
    int i = blockIdx.x * blockDim.x + threadIdx.x;
    if (i >= n4) return;
    float4 v = ((const float4*)src)[i];
    unsigned hx, hy, hz, hw;
    asm("cvt.rna.tf32.f32 %0, %1;" : "=r"(hx) : "f"(v.x));
    asm("cvt.rna.tf32.f32 %0, %1;" : "=r"(hy) : "f"(v.y));
    asm("cvt.rna.tf32.f32 %0, %1;" : "=r"(hz) : "f"(v.z));
    asm("cvt.rna.tf32.f32 %0, %1;" : "=r"(hw) : "f"(v.w));
    float4 h = { __uint_as_float(hx), __uint_as_float(hy),
                 __uint_as_float(hz), __uint_as_float(hw) };
    ((float4*)dst)[i] = h;
}

// -------------------------------------------------------------------------
__global__ void rowsq_kernel(const float* __restrict__ emb,
                             const float* __restrict__ z,
                             int K, int B)
{
    int w    = (blockIdx.x * blockDim.x + threadIdx.x) >> 5;
    int lane = threadIdx.x & 31;
    if (w >= K + B) return;
    const float* src = (w < K) ? (emb + (size_t)w * DDIM)
                               : (z   + (size_t)(w - K) * DDIM);
    float s = 0.f;
#pragma unroll
    for (int t = 0; t < DDIM / 32; t++) {
        float x = src[lane + 32 * t];
        s = fmaf(x, x, s);
    }
#pragma unroll
    for (int off = 16; off > 0; off >>= 1)
        s += __shfl_xor_sync(0xFFFFFFFFu, s, off);
    if (lane == 0) {
        if (w < K) g_ee[w] = s;
        else       g_zz[w - K] = s;
    }
}

// -------------------------------------------------------------------------
__device__ __forceinline__ void cp16(float* sdst, const float* gsrc)
{
    unsigned s = (unsigned)__cvta_generic_to_shared(sdst);
    asm volatile("cp.async.ca.shared.global [%0], [%1], 16;\n" :: "r"(s), "l"(gsrc));
}
__device__ __forceinline__ void cp_commit() { asm volatile("cp.async.commit_group;\n"); }
__device__ __forceinline__ void cp_wait0()  { asm volatile("cp.async.wait_group 0;\n"); }

__device__ __forceinline__ void mma_tf32(float* c, unsigned a0, unsigned a1,
                                         unsigned a2, unsigned a3,
                                         unsigned b0, unsigned b1)
{
    asm volatile(
        "mma.sync.aligned.m16n8k8.row.col.f32.tf32.tf32.f32 "
        "{%0,%1,%2,%3}, {%4,%5,%6,%7}, {%8,%9}, {%0,%1,%2,%3};\n"
        : "+f"(c[0]), "+f"(c[1]), "+f"(c[2]), "+f"(c[3])
        : "r"(a0), "r"(a1), "r"(a2), "r"(a3), "r"(b0), "r"(b1));
}

// Phase 1: 1x tf32 GEMM; per (128-row, 128-col) ktile computes approx q,
// stores q to g_q, tracks per-row running min -> g_rmin.
__global__ __launch_bounds__(256, 1)
void vq_phase1_kernel(int K)
{
    extern __shared__ float smem[];
    __shared__ float sEE[BN];

    const int tid   = threadIdx.x;
    const int wid   = tid >> 5;
    const int lane  = tid & 31;
    const int g     = lane >> 2;
    const int t     = lane & 3;
    const int warpM = wid >> 1;      // 0..3
    const int warpN = wid & 1;       // 0..1
    const int brow  = blockIdx.x * BM;

    float zz_r[4];
#pragma unroll
    for (int a = 0; a < 4; a++)
        zz_r[a] = g_zz[brow + warpM * 32 + (a >> 1) * 16 + (a & 1) * 8 + g];

    float bestv[4];
#pragma unroll
    for (int a = 0; a < 4; a++) bestv[a] = 3.4e38f;

    int cp_m[4], cp_k4[4];
#pragma unroll
    for (int i = 0; i < 4; i++) {
        int idx = tid + i * 256;
        cp_m[i]  = idx >> 3;
        cp_k4[i] = (idx & 7) * 4;
    }

    const int NCH = (K / BN) * (DDIM / BD);   // 1024

    // prologue: chunk 0 -> buffer 0
    {
        float* bA = smem;
        float* bB = smem + ABUF;
#pragma unroll
        for (int i = 0; i < 4; i++) {
            size_t zo = (size_t)(brow + cp_m[i]) * DDIM + cp_k4[i];
            size_t eo = (size_t)(cp_m[i]) * DDIM + cp_k4[i];
            int so = cp_m[i] * ROWP + cp_k4[i];
            cp16(bA + so, g_zt + zo);
            cp16(bB + so, g_et + eo);
        }
        cp_commit();
    }

    float acc[2][8][4];
#pragma unroll
    for (int mt = 0; mt < 2; mt++)
#pragma unroll
        for (int nt = 0; nt < 8; nt++)
#pragma unroll
            for (int r = 0; r < 4; r++) acc[mt][nt][r] = 0.f;

    for (int c = 0; c < NCH; c++) {
        const int dch = c & 15;
        const int kt  = (c >> 4) * BN;
        float* bA = smem + (c & 1) * BUFSZ;
        float* bB = bA + ABUF;

        cp_wait0();
        __syncthreads();

        if (dch == 0 && tid < BN) sEE[tid] = g_ee[kt + tid];

        if (c + 1 < NCH) {
            const int ndch = (c + 1) & 15;
            const int nkt  = ((c + 1) >> 4) * BN;
            const int ndb  = ndch * BD;
            float* nA = smem + ((c + 1) & 1) * BUFSZ;
            float* nB = nA + ABUF;
#pragma unroll
            for (int i = 0; i < 4; i++) {
                size_t zo = (size_t)(brow + cp_m[i]) * DDIM + ndb + cp_k4[i];
                size_t eo = (size_t)(nkt  + cp_m[i]) * DDIM + ndb + cp_k4[i];
                int so = cp_m[i] * ROWP + cp_k4[i];
                cp16(nA + so, g_zt + zo);
                cp16(nB + so, g_et + eo);
            }
            cp_commit();
        }

#pragma unroll
        for (int ks = 0; ks < BD / 8; ks++) {
            const int k8 = ks * 8;
            unsigned AH[2][4];
#pragma unroll
            for (int mt = 0; mt < 2; mt++) {
                int r0 = (warpM * 32 + mt * 16 + g) * ROWP;
                int r8 = r0 + 8 * ROWP;
                AH[mt][0] = __float_as_uint(bA[r0 + k8 + t]);
                AH[mt][1] = __float_as_uint(bA[r8 + k8 + t]);
                AH[mt][2] = __float_as_uint(bA[r0 + k8 + t + 4]);
                AH[mt][3] = __float_as_uint(bA[r8 + k8 + t + 4]);
            }
            unsigned BH[8][2];
#pragma unroll
            for (int nt = 0; nt < 8; nt++) {
                int n0 = (warpN * 64 + nt * 8 + g) * ROWP;
                BH[nt][0] = __float_as_uint(bB[n0 + k8 + t]);
                BH[nt][1] = __float_as_uint(bB[n0 + k8 + t + 4]);
            }
#pragma unroll
            for (int mt = 0; mt < 2; mt++)
#pragma unroll
                for (int nt = 0; nt < 8; nt++)
                    mma_tf32(acc[mt][nt], AH[mt][0], AH[mt][1], AH[mt][2], AH[mt][3],
                             BH[nt][0], BH[nt][1]);
        }

        if (dch == 15) {
            // approx q, running min, stage to smem
            float* stage = smem + STAGE_OFF;
#pragma unroll
            for (int mt = 0; mt < 2; mt++)
#pragma unroll
                for (int i = 0; i < 2; i++) {
                    const int a = mt * 2 + i;
                    const int srow = warpM * 32 + mt * 16 + i * 8 + g;
                    float v = 3.4e38f;
#pragma unroll
                    for (int nt = 0; nt < 8; nt++)
#pragma unroll
                        for (int cc = 0; cc < 2; cc++) {
                            int col = warpN * 64 + nt * 8 + 2 * t + cc;
                            float q = fmaf(-2.f, acc[mt][nt][i * 2 + cc], zz_r[a]) + sEE[col];
                            stage[srow * STROW + col] = q;
                            if (q < v) v = q;
                        }
#pragma unroll
                    for (int off = 1; off < 4; off <<= 1) {
                        float ov = __shfl_xor_sync(0xFFFFFFFFu, v, off);
                        if (ov < v) v = ov;
                    }
                    if (v < bestv[a]) bestv[a] = v;
                }
            // reset accumulators
#pragma unroll
            for (int mt = 0; mt < 2; mt++)
#pragma unroll
                for (int nt = 0; nt < 8; nt++)
#pragma unroll
                    for (int r = 0; r < 4; r++) acc[mt][nt][r] = 0.f;

            __syncthreads();
            // cooperative coalesced store staging -> g_q
#pragma unroll
            for (int i = 0; i < 16; i++) {
                int idx = tid + i * 256;
                int row = idx >> 5;
                int c4  = idx & 31;
                float4 v4 = *(const float4*)&stage[row * STROW + c4 * 4];
                *(float4*)&g_q[(size_t)(brow + row) * K + kt + c4 * 4] = v4;
            }
        }
    }

    // merge the two warpN halves -> per-row approx min
    __syncthreads();
    float* sv = smem + STAGE_OFF;   // reuse staging: [2][128]
    if (t == 0) {
#pragma unroll
        for (int a = 0; a < 4; a++) {
            int row = warpM * 32 + (a >> 1) * 16 + (a & 1) * 8 + g;
            sv[warpN * 128 + row] = bestv[a];
        }
    }
    __syncthreads();
    if (tid < BM) {
        float v0 = sv[tid], v1 = sv[128 + tid];
        g_rmin[brow + tid] = (v1 < v0) ? v1 : v0;
    }
}

// -------------------------------------------------------------------------
// Phase 2: one warp per row. Scan stored approx q; candidates within MARGIN
// of the approx min get an exact fp32 recompute (serial ascending-k fmaf,
// bit-identical to the Round-2 chain); pick min with first-index ties.
// -------------------------------------------------------------------------
__global__ __launch_bounds__(256)
void filter_kernel(const float* __restrict__ z,
                   const float* __restrict__ emb, int K)
{
    const int wid  = threadIdx.x >> 5;
    const int lane = threadIdx.x & 31;
    const int row  = blockIdx.x * 8 + wid;

    const float thresh = g_rmin[row] + MARGIN;
    const float zz     = g_zz[row];
    const float4* zp   = (const float4*)(z + (size_t)row * DDIM);

    float v  = 3.4e38f;
    int   bi = 0x7FFFFFFF;

    for (int it = 0; it < K / 128; it++) {
        int k0 = it * 128 + lane * 4;
        float4 qv = *(const float4*)&g_q[(size_t)row * K + k0];
        float qs[4] = {qv.x, qv.y, qv.z, qv.w};
#pragma unroll
        for (int j = 0; j < 4; j++) {
            if (qs[j] <= thresh) {
                int k = k0 + j;
                const float4* ep = (const float4*)(emb + (size_t)k * DDIM);
                float accd = 0.f;
#pragma unroll 4
                for (int d = 0; d < DDIM / 4; d++) {
                    float4 za = zp[d], ea = ep[d];
                    accd = fmaf(za.x, ea.x, accd);
                    accd = fmaf(za.y, ea.y, accd);
                    accd = fmaf(za.z, ea.z, accd);
                    accd = fmaf(za.w, ea.w, accd);
                }
                float q = fmaf(-2.f, accd, zz) + g_ee[k];
                if (q < v || (q == v && k < bi)) { v = q; bi = k; }
            }
        }
    }
#pragma unroll
    for (int off = 16; off > 0; off >>= 1) {
        float ov = __shfl_xor_sync(0xFFFFFFFFu, v, off);
        int   oi = __shfl_xor_sync(0xFFFFFFFFu, bi, off);
        if (ov < v || (ov == v && oi < bi)) { v = ov; bi = oi; }
    }
    if (lane == 0) g_best[row] = bi;
}

// -------------------------------------------------------------------------
__global__ void gather_loss_kernel(const float* __restrict__ z,
                                   const float* __restrict__ emb,
                                   float* __restrict__ out_zq,
                                   float* __restrict__ out_idx,
                                   int B)
{
    __shared__ double sred[128];
    const int tid = threadIdx.x;
    double lsum = 0.0;

    for (int r = 0; r < 32; r++) {
        int b   = blockIdx.x * 32 + r;
        int idx = g_best[b];
        if (tid == 0 && out_idx) out_idx[b] = (float)idx;

        float4 zv = ((const float4*)(z   + (size_t)b   * DDIM))[tid];
        float4 ev = ((const float4*)(emb + (size_t)idx * DDIM))[tid];
        float4 o;
        float dx;
        dx = ev.x - zv.x; o.x = zv.x + dx; lsum += (double)dx * (double)dx;
        dx = ev.y - zv.y; o.y = zv.y + dx; lsum += (double)dx * (double)dx;
        dx = ev.z - zv.z; o.z = zv.z + dx; lsum += (double)dx * (double)dx;
        dx = ev.w - zv.w; o.w = zv.w + dx; lsum += (double)dx * (double)dx;
        ((float4*)(out_zq + (size_t)b * DDIM))[tid] = o;
    }

    sred[tid] = lsum;
    __syncthreads();
#pragma unroll
    for (int s = 64; s > 0; s >>= 1) {
        if (tid < s) sred[tid] += sred[tid + s];
        __syncthreads();
    }
    if (tid == 0) g_part[blockIdx.x] = sred[0];
}

__global__ void finalize_kernel(float* __restrict__ out_loss, int nparts, double scale)
{
    double s = 0.0;
    for (int i = 0; i < nparts; i++) s += g_part[i];
    *out_loss = (float)(s * scale);
}

// -------------------------------------------------------------------------
extern "C" void kernel_launch(void* const* d_in, const int* in_sizes, int n_in,
                              void* d_out, int out_size)
{
    const float* z   = (const float*)d_in[0];
    const float* emb = (const float*)d_in[1];
    int B = in_sizes[0] / DDIM;   // 16384
    int K = in_sizes[1] / DDIM;   // 8192

    float* out      = (float*)d_out;
    float* out_zq   = out;
    float* out_idx  = ((size_t)out_size >= (size_t)B * DDIM + (size_t)B)
                        ? out + (size_t)B * DDIM : nullptr;
    float* out_loss = ((size_t)out_size >= (size_t)B * DDIM + (size_t)B + 1)
                        ? out + (size_t)B * DDIM + B : nullptr;

    float *zt, *et;
    cudaGetSymbolAddress((void**)&zt, g_zt);
    cudaGetSymbolAddress((void**)&et, g_et);

    static int smem_set = 0;
    const int dyn_smem = (2 * BUFSZ + 128 * STROW) * 4;   // 141312 B
    if (!smem_set) {
        cudaFuncSetAttribute(vq_phase1_kernel,
                             cudaFuncAttributeMaxDynamicSharedMemorySize, dyn_smem);
        smem_set = 1;
    }

    int nz4 = B * DDIM / 4, ne4 = K * DDIM / 4;
    split_tf32_kernel<<<(nz4 + 255) / 256, 256>>>(z, zt, nz4);
    split_tf32_kernel<<<(ne4 + 255) / 256, 256>>>(emb, et, ne4);
    rowsq_kernel<<<((K + B) * 32 + 255) / 256, 256>>>(emb, z, K, B);

    vq_phase1_kernel<<<B / BM, 256, dyn_smem>>>(K);
    filter_kernel<<<B / 8, 256>>>(z, emb, K);

    int gblocks = B / 32;
    gather_loss_kernel<<<gblocks, 128>>>(z, emb, out_zq, out_idx, B);
    if (out_loss)
        finalize_kernel<<<1, 1>>>(out_loss, gblocks, 1.25 / ((double)B * (double)DDIM));
}

// round 5
// speedup vs baseline: 1.9100x; 1.1177x over previous
#include <cuda_runtime.h>
#include <cuda_bf16.h>
#include <cuda_fp16.h>
#include <cstdint>
#include <cstddef>

// VectorQuantizer, two-phase:
//   Phase 1: bf16 tensor-core GEMM (m16n8k16) -> screen s[b,k] = ee - 2*G_bf16
//            stored as fp16 (256 MB) + per-row fp32 min.
//   Phase 2: exact fp32 rescue (bit-identical to the passing Round-2 chain) on all
//            candidates within MARGIN of the approx min -> exact argmin w/ ties.
//   Margin 2e-3 >> worst-case bf16 screen error (~3.9e-4) + fp16 store error.
// Output: [ z_q_st (B*512) | indices as float (B) | vq_loss (1) ]

#define DDIM 512
#define BM 128
#define BN 128
#define BD 32            // D-chunk in elements

#define NB 16384
#define NK 8192

#define SA 40                    // smem row stride in halves (80B, conflict-free)
#define ABUF_H (128 * SA)        // one operand tile, halves
#define BUF_H  (2 * ABUF_H)      // A+B per pipeline buffer
#define STAGE_OFF_H (2 * BUF_H)  // fp16 staging after the two buffers
#define STROW_H 136              // staging row stride in halves (128 + 8 pad)

#define MARGIN 2e-3f

__device__ float  g_ee[NK];
__device__ float  g_zz[NB];
__device__ float  g_rmin[NB];
__device__ int    g_best[NB];
__device__ double g_part[512];

__device__ __nv_bfloat16 g_zb[NB * DDIM];       // bf16 z
__device__ __nv_bfloat16 g_eb[NK * DDIM];       // bf16 emb
__device__ __half        g_s[(size_t)NB * NK];  // fp16 screen, 256 MB

// -------------------------------------------------------------------------
__global__ void to_bf16_kernel(const float* __restrict__ src,
                               __nv_bfloat16* __restrict__ dst, int n4)
{
    int i = blockIdx.x * blockDim.x + threadIdx.x;
    if (i >= n4) return;
    float4 v = ((const float4*)src)[i];
    __nv_bfloat162 p0 = __floats2bfloat162_rn(v.x, v.y);
    __nv_bfloat162 p1 = __floats2bfloat162_rn(v.z, v.w);
    uint2 w;
    w.x = *reinterpret_cast<unsigned*>(&p0);
    w.y = *reinterpret_cast<unsigned*>(&p1);
    ((uint2*)dst)[i] = w;
}

// -------------------------------------------------------------------------
__global__ void rowsq_kernel(const float* __restrict__ emb,
                             const float* __restrict__ z,
                             int K, int B)
{
    int w    = (blockIdx.x * blockDim.x + threadIdx.x) >> 5;
    int lane = threadIdx.x & 31;
    if (w >= K + B) return;
    const float* src = (w < K) ? (emb + (size_t)w * DDIM)
                               : (z   + (size_t)(w - K) * DDIM);
    float s = 0.f;
#pragma unroll
    for (int t = 0; t < DDIM / 32; t++) {
        float x = src[lane + 32 * t];
        s = fmaf(x, x, s);
    }
#pragma unroll
    for (int off = 16; off > 0; off >>= 1)
        s += __shfl_xor_sync(0xFFFFFFFFu, s, off);
    if (lane == 0) {
        if (w < K) g_ee[w] = s;
        else       g_zz[w - K] = s;
    }
}

// -------------------------------------------------------------------------
__device__ __forceinline__ void cp16(__half* sdst, const void* gsrc)
{
    unsigned s = (unsigned)__cvta_generic_to_shared(sdst);
    asm volatile("cp.async.ca.shared.global [%0], [%1], 16;\n" :: "r"(s), "l"(gsrc));
}
__device__ __forceinline__ void cp_commit() { asm volatile("cp.async.commit_group;\n"); }
__device__ __forceinline__ void cp_wait0()  { asm volatile("cp.async.wait_group 0;\n"); }

__device__ __forceinline__ void mma_bf16(float* c, unsigned a0, unsigned a1,
                                         unsigned a2, unsigned a3,
                                         unsigned b0, unsigned b1)
{
    asm volatile(
        "mma.sync.aligned.m16n8k16.row.col.f32.bf16.bf16.f32 "
        "{%0,%1,%2,%3}, {%4,%5,%6,%7}, {%8,%9}, {%0,%1,%2,%3};\n"
        : "+f"(c[0]), "+f"(c[1]), "+f"(c[2]), "+f"(c[3])
        : "r"(a0), "r"(a1), "r"(a2), "r"(a3), "r"(b0), "r"(b1));
}

// Phase 1: bf16 GEMM; per (128-row, 128-col) ktile computes s = ee - 2G,
// stores fp16 s to g_s, tracks per-row fp32 running min -> g_rmin.
__global__ __launch_bounds__(256, 1)
void vq_phase1_kernel(int K)
{
    extern __shared__ __half smem[];
    __shared__ float sEE[BN];

    const int tid   = threadIdx.x;
    const int wid   = tid >> 5;
    const int lane  = tid & 31;
    const int g     = lane >> 2;
    const int t     = lane & 3;
    const int warpM = wid >> 1;      // 0..3
    const int warpN = wid & 1;       // 0..1
    const int brow  = blockIdx.x * BM;

    float bestv[4];
#pragma unroll
    for (int a = 0; a < 4; a++) bestv[a] = 3.4e38f;

    // cp.async mapping: per operand 128 rows x 4 chunks of 16B; 2 per thread.
    int cp_r[2], cp_c[2];
#pragma unroll
    for (int i = 0; i < 2; i++) {
        int idx = tid + i * 256;
        cp_r[i] = idx >> 2;          // 0..127
        cp_c[i] = (idx & 3) * 8;     // half offset within row
    }

    const int NCH = (K / BN) * (DDIM / BD);   // 1024

    // prologue: chunk 0 -> buffer 0
    {
        __half* bA = smem;
        __half* bB = smem + ABUF_H;
#pragma unroll
        for (int i = 0; i < 2; i++) {
            cp16(bA + cp_r[i] * SA + cp_c[i],
                 g_zb + (size_t)(brow + cp_r[i]) * DDIM + cp_c[i]);
            cp16(bB + cp_r[i] * SA + cp_c[i],
                 g_eb + (size_t)cp_r[i] * DDIM + cp_c[i]);
        }
        cp_commit();
    }

    float acc[2][8][4];
#pragma unroll
    for (int mt = 0; mt < 2; mt++)
#pragma unroll
        for (int nt = 0; nt < 8; nt++)
#pragma unroll
            for (int r = 0; r < 4; r++) acc[mt][nt][r] = 0.f;

    for (int c = 0; c < NCH; c++) {
        const int dch = c & 15;
        const int kt  = (c >> 4) * BN;
        __half* bA = smem + (c & 1) * BUF_H;
        __half* bB = bA + ABUF_H;

        cp_wait0();
        __syncthreads();

        if (dch == 0 && tid < BN) sEE[tid] = g_ee[kt + tid];

        if (c + 1 < NCH) {
            const int ndb = ((c + 1) & 15) * BD;
            const int nkt = ((c + 1) >> 4) * BN;
            __half* nA = smem + ((c + 1) & 1) * BUF_H;
            __half* nB = nA + ABUF_H;
#pragma unroll
            for (int i = 0; i < 2; i++) {
                cp16(nA + cp_r[i] * SA + cp_c[i],
                     g_zb + (size_t)(brow + cp_r[i]) * DDIM + ndb + cp_c[i]);
                cp16(nB + cp_r[i] * SA + cp_c[i],
                     g_eb + (size_t)(nkt + cp_r[i]) * DDIM + ndb + cp_c[i]);
            }
            cp_commit();
        }

        // compute: BD=32 halves = 2 k16 steps
#pragma unroll
        for (int ks = 0; ks < 2; ks++) {
            const int kb = ks * 16;   // half offset
            unsigned A[2][4];
#pragma unroll
            for (int mt = 0; mt < 2; mt++) {
                int r0 = (warpM * 32 + mt * 16 + g) * SA + kb + 2 * t;
                int r8 = r0 + 8 * SA;
                A[mt][0] = *(const unsigned*)&bA[r0];
                A[mt][1] = *(const unsigned*)&bA[r8];
                A[mt][2] = *(const unsigned*)&bA[r0 + 8];
                A[mt][3] = *(const unsigned*)&bA[r8 + 8];
            }
            unsigned Bf[8][2];
#pragma unroll
            for (int nt = 0; nt < 8; nt++) {
                int n0 = (warpN * 64 + nt * 8 + g) * SA + kb + 2 * t;
                Bf[nt][0] = *(const unsigned*)&bB[n0];
                Bf[nt][1] = *(const unsigned*)&bB[n0 + 8];
            }
#pragma unroll
            for (int mt = 0; mt < 2; mt++)
#pragma unroll
                for (int nt = 0; nt < 8; nt++)
                    mma_bf16(acc[mt][nt], A[mt][0], A[mt][1], A[mt][2], A[mt][3],
                             Bf[nt][0], Bf[nt][1]);
        }

        if (dch == 15) {
            __half* stage = smem + STAGE_OFF_H;
#pragma unroll
            for (int mt = 0; mt < 2; mt++)
#pragma unroll
                for (int i = 0; i < 2; i++) {
                    const int a = mt * 2 + i;
                    const int srow = warpM * 32 + mt * 16 + i * 8 + g;
                    float v = 3.4e38f;
#pragma unroll
                    for (int nt = 0; nt < 8; nt++) {
                        int col = warpN * 64 + nt * 8 + 2 * t;
                        float s0 = fmaf(-2.f, acc[mt][nt][i * 2 + 0], sEE[col]);
                        float s1 = fmaf(-2.f, acc[mt][nt][i * 2 + 1], sEE[col + 1]);
                        *(__half2*)&stage[srow * STROW_H + col] =
                            __floats2half2_rn(s0, s1);
                        float m = (s0 < s1) ? s0 : s1;
                        if (m < v) v = m;
                    }
#pragma unroll
                    for (int off = 1; off < 4; off <<= 1) {
                        float ov = __shfl_xor_sync(0xFFFFFFFFu, v, off);
                        if (ov < v) v = ov;
                    }
                    if (v < bestv[a]) bestv[a] = v;
                }
#pragma unroll
            for (int mt = 0; mt < 2; mt++)
#pragma unroll
                for (int nt = 0; nt < 8; nt++)
#pragma unroll
                    for (int r = 0; r < 4; r++) acc[mt][nt][r] = 0.f;

            __syncthreads();
            // cooperative store staging -> g_s (fp16), 8 float4 per thread
#pragma unroll
            for (int i = 0; i < 8; i++) {
                int idx = tid + i * 256;
                int row = idx >> 4;
                int c8  = idx & 15;
                float4 v4 = *(const float4*)&stage[row * STROW_H + c8 * 8];
                *(float4*)&g_s[(size_t)(brow + row) * K + kt + c8 * 8] = v4;
            }
        }
    }

    // merge the two warpN halves -> per-row approx min
    __syncthreads();
    float* sv = (float*)(smem + STAGE_OFF_H);
    if (t == 0) {
#pragma unroll
        for (int a = 0; a < 4; a++) {
            int row = warpM * 32 + (a >> 1) * 16 + (a & 1) * 8 + g;
            sv[warpN * 128 + row] = bestv[a];
        }
    }
    __syncthreads();
    if (tid < BM) {
        float v0 = sv[tid], v1 = sv[128 + tid];
        g_rmin[brow + tid] = (v1 < v0) ? v1 : v0;
    }
}

// -------------------------------------------------------------------------
// Phase 2: one warp per row. Scan fp16 screen; candidates within MARGIN of
// the approx min get the exact fp32 recompute (bit-identical to Round 2).
// -------------------------------------------------------------------------
__global__ __launch_bounds__(256)
void filter_kernel(const float* __restrict__ z,
                   const float* __restrict__ emb, int K)
{
    const int wid  = threadIdx.x >> 5;
    const int lane = threadIdx.x & 31;
    const int row  = blockIdx.x * 8 + wid;

    const float thresh = g_rmin[row] + MARGIN;
    const float zz     = g_zz[row];
    const float4* zp   = (const float4*)(z + (size_t)row * DDIM);
    const __half* qrow = g_s + (size_t)row * K;

    float v  = 3.4e38f;
    int   bi = 0x7FFFFFFF;

    for (int it = 0; it < K / 256; it++) {
        int k0 = it * 256 + lane * 8;
        uint4 u = *(const uint4*)&qrow[k0];
        unsigned uw[4] = {u.x, u.y, u.z, u.w};
#pragma unroll
        for (int p = 0; p < 4; p++) {
            float2 f = __half22float2(*reinterpret_cast<__half2*>(&uw[p]));
            float sv[2] = {f.x, f.y};
#pragma unroll
            for (int j = 0; j < 2; j++) {
                if (sv[j] <= thresh) {
                    int k = k0 + p * 2 + j;
                    const float4* ep = (const float4*)(emb + (size_t)k * DDIM);
                    float accd = 0.f;
#pragma unroll 4
                    for (int d = 0; d < DDIM / 4; d++) {
                        float4 za = zp[d], ea = ep[d];
                        accd = fmaf(za.x, ea.x, accd);
                        accd = fmaf(za.y, ea.y, accd);
                        accd = fmaf(za.z, ea.z, accd);
                        accd = fmaf(za.w, ea.w, accd);
                    }
                    float q = fmaf(-2.f, accd, zz) + g_ee[k];
                    if (q < v || (q == v && k < bi)) { v = q; bi = k; }
                }
            }
        }
    }
#pragma unroll
    for (int off = 16; off > 0; off >>= 1) {
        float ov = __shfl_xor_sync(0xFFFFFFFFu, v, off);
        int   oi = __shfl_xor_sync(0xFFFFFFFFu, bi, off);
        if (ov < v || (ov == v && oi < bi)) { v = ov; bi = oi; }
    }
    if (lane == 0) g_best[row] = bi;
}

// -------------------------------------------------------------------------
__global__ void gather_loss_kernel(const float* __restrict__ z,
                                   const float* __restrict__ emb,
                                   float* __restrict__ out_zq,
                                   float* __restrict__ out_idx,
                                   int B)
{
    __shared__ double sred[128];
    const int tid = threadIdx.x;
    double lsum = 0.0;

    for (int r = 0; r < 32; r++) {
        int b   = blockIdx.x * 32 + r;
        int idx = g_best[b];
        if (tid == 0 && out_idx) out_idx[b] = (float)idx;

        float4 zv = ((const float4*)(z   + (size_t)b   * DDIM))[tid];
        float4 ev = ((const float4*)(emb + (size_t)idx * DDIM))[tid];
        float4 o;
        float dx;
        dx = ev.x - zv.x; o.x = zv.x + dx; lsum += (double)dx * (double)dx;
        dx = ev.y - zv.y; o.y = zv.y + dx; lsum += (double)dx * (double)dx;
        dx = ev.z - zv.z; o.z = zv.z + dx; lsum += (double)dx * (double)dx;
        dx = ev.w - zv.w; o.w = zv.w + dx; lsum += (double)dx * (double)dx;
        ((float4*)(out_zq + (size_t)b * DDIM))[tid] = o;
    }

    sred[tid] = lsum;
    __syncthreads();
#pragma unroll
    for (int s = 64; s > 0; s >>= 1) {
        if (tid < s) sred[tid] += sred[tid + s];
        __syncthreads();
    }
    if (tid == 0) g_part[blockIdx.x] = sred[0];
}

__global__ void finalize_kernel(float* __restrict__ out_loss, int nparts, double scale)
{
    double s = 0.0;
    for (int i = 0; i < nparts; i++) s += g_part[i];
    *out_loss = (float)(s * scale);
}

// -------------------------------------------------------------------------
extern "C" void kernel_launch(void* const* d_in, const int* in_sizes, int n_in,
                              void* d_out, int out_size)
{
    const float* z   = (const float*)d_in[0];
    const float* emb = (const float*)d_in[1];
    int B = in_sizes[0] / DDIM;   // 16384
    int K = in_sizes[1] / DDIM;   // 8192

    float* out      = (float*)d_out;
    float* out_zq   = out;
    float* out_idx  = ((size_t)out_size >= (size_t)B * DDIM + (size_t)B)
                        ? out + (size_t)B * DDIM : nullptr;
    float* out_loss = ((size_t)out_size >= (size_t)B * DDIM + (size_t)B + 1)
                        ? out + (size_t)B * DDIM + B : nullptr;

    __nv_bfloat16 *zb, *eb;
    cudaGetSymbolAddress((void**)&zb, g_zb);
    cudaGetSymbolAddress((void**)&eb, g_eb);

    static int smem_set = 0;
    const int dyn_smem = (2 * BUF_H + 128 * STROW_H) * 2;   // 75776 B
    if (!smem_set) {
        cudaFuncSetAttribute(vq_phase1_kernel,
                             cudaFuncAttributeMaxDynamicSharedMemorySize, dyn_smem);
        smem_set = 1;
    }

    int nz4 = B * DDIM / 4, ne4 = K * DDIM / 4;
    to_bf16_kernel<<<(nz4 + 255) / 256, 256>>>(z, zb, nz4);
    to_bf16_kernel<<<(ne4 + 255) / 256, 256>>>(emb, eb, ne4);
    rowsq_kernel<<<((K + B) * 32 + 255) / 256, 256>>>(emb, z, K, B);

    vq_phase1_kernel<<<B / BM, 256, dyn_smem>>>(K);
    filter_kernel<<<B / 8, 256>>>(z, emb, K);

    int gblocks = B / 32;
    gather_loss_kernel<<<gblocks, 128>>>(z, emb, out_zq, out_idx, B);
    if (out_loss)
        finalize_kernel<<<1, 1>>>(out_loss, gblocks, 1.25 / ((double)B * (double)DDIM));
}